// round 4
// baseline (speedup 1.0000x reference)
#include <cuda_runtime.h>

typedef unsigned long long ull;

#define B_DIM    128
#define IN_DIM   1024
#define OUT_DIM  1024
#define KSPLIT   8
#define K_PER_CTA 128      // IN_DIM / KSPLIT
#define K_CHUNK  64        // smem stage depth
#define O_TILE   64
#define THREADS  512
#define GRID     (KSPLIT * (OUT_DIM / O_TILE))   // 128 CTAs, one wave

// 4 MB fp32 partial sums: g_part[ks][b][o]
__device__ float g_part[KSPLIT * B_DIM * OUT_DIM];
__device__ unsigned int g_ctr;   // zero-init; monotonic across replays

__device__ __forceinline__ ull fma2(ull a, ull b, ull c) {
    ull d;
    asm("fma.rn.f32x2 %0, %1, %2, %3;" : "=l"(d) : "l"(a), "l"(b), "l"(c));
    return d;
}
__device__ __forceinline__ ull dup2(float w) {
    unsigned u = __float_as_uint(w);
    ull d;
    asm("mov.b64 %0, {%1, %1};" : "=l"(d) : "r"(u));
    return d;
}
__device__ __forceinline__ float lo32(ull v) { return __uint_as_float((unsigned)v); }
__device__ __forceinline__ float hi32(ull v) { return __uint_as_float((unsigned)(v >> 32)); }

// ---------------------------------------------------------------------------
// Fused persistent kernel: split-K GEMM (W gathered from means[dest]) ->
// device-wide barrier -> fold partials + bias -> out.
// ---------------------------------------------------------------------------
__global__ void __launch_bounds__(THREADS)
sic_fused(const float* __restrict__ x, const float* __restrict__ means,
          const float* __restrict__ bias, const int* __restrict__ dest,
          float* __restrict__ out)
{
    __shared__ __align__(16) float xs[K_CHUNK * B_DIM];   // [kk][b], 16B-chunk swizzled
    __shared__ __align__(16) float ws[K_CHUNK * O_TILE];  // [kk][o], 16B-chunk swizzled

    const int tid = threadIdx.x;
    const int ks  = blockIdx.x & (KSPLIT - 1);
    const int o0  = (blockIdx.x >> 3) * O_TILE;

    // Microtile mapping: o fastest across lanes (coalesced stores, ws reads
    // span a full row), b broadcast within half-warp (xs reads broadcast).
    const int o_base = (tid & 15) * 4;
    const int b_base = (tid >> 4) * 4;
    const int wc0 = tid & 15;          // ws 16B chunk
    const int xc0 = tid >> 4;          // xs 16B chunk (0..31)

    ull acc[8];  // acc[oi*2 + p]: outputs o_base+oi, batches b_base+2p(+1)
#pragma unroll
    for (int i = 0; i < 8; i++) acc[i] = 0ull;

    for (int kc = 0; kc < K_PER_CTA / K_CHUNK; kc++) {
        const int k0 = ks * K_PER_CTA + kc * K_CHUNK;
        if (kc) __syncthreads();   // previous chunk's reads done

        // ---- x chunk -> smem transposed + swizzled ----
        for (int s = tid; s < B_DIM * (K_CHUNK / 4); s += THREADS) {
            const int b  = s >> 4;
            const int kv = (s & 15) << 2;
            const float4 v = *reinterpret_cast<const float4*>(x + b * IN_DIM + k0 + kv);
            const int bc = b >> 2, bl = b & 3;
            xs[(kv + 0) * B_DIM + ((((bc ^ (kv + 0)) & 31) << 2) | bl)] = v.x;
            xs[(kv + 1) * B_DIM + ((((bc ^ (kv + 1)) & 31) << 2) | bl)] = v.y;
            xs[(kv + 2) * B_DIM + ((((bc ^ (kv + 2)) & 31) << 2) | bl)] = v.z;
            xs[(kv + 3) * B_DIM + ((((bc ^ (kv + 3)) & 31) << 2) | bl)] = v.w;
        }
        // ---- W chunk gather: ws[kk][o] = means[dest[(o0+o)*IN + k0+kk]] ----
        for (int s = tid; s < O_TILE * (K_CHUNK / 4); s += THREADS) {
            const int o  = s >> 4;
            const int kv = (s & 15) << 2;
            const int4 dd = *reinterpret_cast<const int4*>(
                dest + (size_t)(o0 + o) * IN_DIM + k0 + kv);
            const int oc = o >> 2, ol = o & 3;
            ws[(kv + 0) * O_TILE + ((((oc ^ (kv + 0)) & 15) << 2) | ol)] = means[dd.x];
            ws[(kv + 1) * O_TILE + ((((oc ^ (kv + 1)) & 15) << 2) | ol)] = means[dd.y];
            ws[(kv + 2) * O_TILE + ((((oc ^ (kv + 2)) & 15) << 2) | ol)] = means[dd.z];
            ws[(kv + 3) * O_TILE + ((((oc ^ (kv + 3)) & 15) << 2) | ol)] = means[dd.w];
        }
        __syncthreads();

        // ---- main loop: fma-bound, packed f32x2 over batch pairs ----
#pragma unroll 8
        for (int kk = 0; kk < K_CHUNK; kk++) {
            const float* xrow = xs + kk * B_DIM;
            const ulonglong2 xa = *reinterpret_cast<const ulonglong2*>(
                xrow + (((xc0 ^ kk) & 31) << 2));
            const float4 wv = *reinterpret_cast<const float4*>(
                ws + kk * O_TILE + (((wc0 ^ kk) & 15) << 2));
            const ull w0 = dup2(wv.x), w1 = dup2(wv.y), w2 = dup2(wv.z), w3 = dup2(wv.w);
            acc[0] = fma2(xa.x, w0, acc[0]);
            acc[1] = fma2(xa.y, w0, acc[1]);
            acc[2] = fma2(xa.x, w1, acc[2]);
            acc[3] = fma2(xa.y, w1, acc[3]);
            acc[4] = fma2(xa.x, w2, acc[4]);
            acc[5] = fma2(xa.y, w2, acc[5]);
            acc[6] = fma2(xa.x, w3, acc[6]);
            acc[7] = fma2(xa.y, w3, acc[7]);
        }
    }

    // ---- partials out: contiguous-o float4 per store, fully coalesced ----
    {
        float* base = g_part + ((size_t)(ks * B_DIM + b_base)) * OUT_DIM + o0 + o_base;
#pragma unroll
        for (int p = 0; p < 2; p++) {
            float4 vlo, vhi;
            vlo.x = lo32(acc[p]);      vhi.x = hi32(acc[p]);
            vlo.y = lo32(acc[2 + p]);  vhi.y = hi32(acc[2 + p]);
            vlo.z = lo32(acc[4 + p]);  vhi.z = hi32(acc[4 + p]);
            vlo.w = lo32(acc[6 + p]);  vhi.w = hi32(acc[6 + p]);
            *reinterpret_cast<float4*>(base + (size_t)(2 * p)     * OUT_DIM) = vlo;
            *reinterpret_cast<float4*>(base + (size_t)(2 * p + 1) * OUT_DIM) = vhi;
        }
    }

    // ---- device-wide barrier (monotonic counter: replay-safe, no reset) ----
    __threadfence();
    __syncthreads();
    if (tid == 0) {
        const unsigned val    = atomicAdd(&g_ctr, 1u) + 1u;
        const unsigned target = ((val - 1u) / GRID + 1u) * GRID;
        while (*(volatile unsigned*)&g_ctr < target) { }
    }
    __syncthreads();
    __threadfence();

    // ---- reduce: 65536 threads, float2 each; partials are L2-hot ----
    {
        const int gid = blockIdx.x * THREADS + tid;        // 0..65535
        const int off = gid * 2;                           // b*1024 + o
        const int o   = off & (OUT_DIM - 1);
        float2 a = make_float2(0.f, 0.f);
#pragma unroll
        for (int k = 0; k < KSPLIT; k++) {
            const float2 v = *reinterpret_cast<const float2*>(
                g_part + (size_t)k * (B_DIM * OUT_DIM) + off);
            a.x += v.x; a.y += v.y;
        }
        const float2 bb = *reinterpret_cast<const float2*>(bias + o);
        a.x += bb.x; a.y += bb.y;
        *reinterpret_cast<float2*>(out + off) = a;
    }
}

extern "C" void kernel_launch(void* const* d_in, const int* in_sizes, int n_in,
                              void* d_out, int out_size)
{
    (void)in_sizes; (void)n_in; (void)out_size;
    const float* x     = (const float*)d_in[0];   // [128,1024] f32
    const float* means = (const float*)d_in[1];   // [1024,16]  f32
    const float* bias  = (const float*)d_in[2];   // [1024]     f32
    // d_in[3] = col_idx (identity layout per row; unused)
    const int*   dest  = (const int*)d_in[4];     // [1024*1024] i32

    sic_fused<<<GRID, THREADS>>>(x, means, bias, dest, (float*)d_out);
}